// round 9
// baseline (speedup 1.0000x reference)
#include <cuda_runtime.h>
#include <cuda_bf16.h>
#include <cstdint>

#define B_   2048
#define T_   200
#define D_   128
#define H_   128
#define M_   (B_ * T_)          // 409600 rows

// ---------------- scratch (static device arrays; no allocation) ----------------
__device__ float g_Gx[(size_t)M_ * 256];   // x-part of gate pre-activations (NO bias)
__device__ float g_Cx[(size_t)M_ * 128];   // x-part of candidate pre-activations (NO bias)
__device__ int   g_perm[B_];
__device__ int   g_sls[B_];
// Full W^T hi/lo: [n (384)][k (256)].  k 0..127 = x-part, 128..255 = h-part
__device__ __align__(16) __nv_bfloat16 g_WThi[384 * 256];
__device__ __align__(16) __nv_bfloat16 g_WTlo[384 * 256];

// ---------------- math helpers ---------------------------------------------------
__device__ __forceinline__ float sigmoid_fast(float x) {
    float e;
    asm("ex2.approx.f32 %0, %1;" : "=f"(e) : "f"(-1.4426950408889634f * x));
    float r;
    asm("rcp.approx.f32 %0, %1;" : "=f"(r) : "f"(1.0f + e));
    return r;
}
__device__ __forceinline__ float tanh_fast(float x) {
    return fmaf(2.0f, sigmoid_fast(2.0f * x), -1.0f);
}
__device__ __forceinline__ uint32_t bf16pack(float a, float b) {
    __nv_bfloat16 ha = __float2bfloat16(a), hb = __float2bfloat16(b);
    return ((uint32_t)__bfloat16_as_ushort(hb) << 16) | __bfloat16_as_ushort(ha);
}
__device__ __forceinline__ uint32_t bf16res(float a, float b, uint32_t hi) {
    float ra = a - __bfloat162float(__ushort_as_bfloat16((unsigned short)(hi & 0xFFFF)));
    float rb = b - __bfloat162float(__ushort_as_bfloat16((unsigned short)(hi >> 16)));
    return bf16pack(ra, rb);
}
__device__ __forceinline__ uint32_t smem_u32(const void* p) {
    uint32_t a;
    asm("{ .reg .u64 t; cvta.to.shared.u64 t, %1; cvt.u32.u64 %0, t; }" : "=r"(a) : "l"(p));
    return a;
}

// ---------------- warp-level bf16 MMA + ldmatrix (sm_80/75+, legal) --------------
__device__ __forceinline__ void mma16816(float* c,
    uint32_t a0, uint32_t a1, uint32_t a2, uint32_t a3,
    uint32_t b0, uint32_t b1)
{
    asm volatile(
        "mma.sync.aligned.m16n8k16.row.col.f32.bf16.bf16.f32 "
        "{%0,%1,%2,%3}, {%4,%5,%6,%7}, {%8,%9}, {%0,%1,%2,%3};"
        : "+f"(c[0]), "+f"(c[1]), "+f"(c[2]), "+f"(c[3])
        : "r"(a0), "r"(a1), "r"(a2), "r"(a3), "r"(b0), "r"(b1));
}
__device__ __forceinline__ void ldsm_x4(uint32_t& r0, uint32_t& r1, uint32_t& r2,
                                        uint32_t& r3, uint32_t addr) {
    asm volatile("ldmatrix.sync.aligned.m8n8.x4.shared.b16 {%0,%1,%2,%3}, [%4];"
                 : "=r"(r0), "=r"(r1), "=r"(r2), "=r"(r3) : "r"(addr));
}
__device__ __forceinline__ void ldsm_x2(uint32_t& r0, uint32_t& r1, uint32_t addr) {
    asm volatile("ldmatrix.sync.aligned.m8n8.x2.shared.b16 {%0,%1}, [%2];"
                 : "=r"(r0), "=r"(r1) : "r"(addr));
}
__device__ __forceinline__ void cpasync16(uint32_t dst, const void* src) {
    asm volatile("cp.async.cg.shared.global [%0], [%1], 16;" :: "r"(dst), "l"(src));
}
#define CPASYNC_COMMIT() asm volatile("cp.async.commit_group;" ::: "memory")
#define CPASYNC_WAIT(N)  asm volatile("cp.async.wait_group %0;" :: "n"(N) : "memory")

// =============================================================================
// Kernel 0a: FULL W transpose + bf16 hi/lo split. WT[n][k] = W[k][n], k 0..255.
// =============================================================================
__global__ void __launch_bounds__(256) augru_wprep(
    const float* __restrict__ Wg, const float* __restrict__ Wc,
    __nv_bfloat16* __restrict__ WThi, __nv_bfloat16* __restrict__ WTlo)
{
    __shared__ float s[32][33];
    const int n0 = blockIdx.x * 32;
    const int tx = threadIdx.x & 31, ty = threadIdx.x >> 5;
    for (int k0 = 0; k0 < 256; k0 += 32) {
        for (int rr = 0; rr < 32; rr += 8) {
            int k = k0 + ty + rr, n = n0 + tx;
            s[ty + rr][tx] = (n0 < 256) ? Wg[(size_t)k * 256 + n]
                                        : Wc[(size_t)k * 128 + (n - 256)];
        }
        __syncthreads();
        for (int rr = 0; rr < 32; rr += 8) {
            int n = n0 + ty + rr, k = k0 + tx;
            float v = s[tx][ty + rr];
            __nv_bfloat16 hi = __float2bfloat16(v);
            float lo = v - __bfloat162float(hi);
            WThi[(size_t)n * 256 + k] = hi;
            WTlo[(size_t)n * 256 + k] = __float2bfloat16(lo);
        }
        __syncthreads();
    }
}

// =============================================================================
// Kernel 0b: parallel deterministic sort by seq_len, DESCENDING.
// =============================================================================
__global__ void __launch_bounds__(256) augru_sort(const int* __restrict__ seqlen,
                                                  int* __restrict__ perm,
                                                  int* __restrict__ sls)
{
    __shared__ int sl[B_];
    const int tid = threadIdx.x;
    for (int i = tid; i < B_; i += 256) sl[i] = seqlen[i];
    __syncthreads();
    const int b = blockIdx.x * 256 + tid;
    const int v = sl[b];
    int pos = 0;
#pragma unroll 8
    for (int j = 0; j < B_; j++) {
        int u = sl[j];
        pos += (u > v) || (u == v && j < b);
    }
    perm[pos] = b;
    sls[pos]  = v;
}

// =============================================================================
// Kernel 1: merged HMMA precompute. ONE block per 128-row tile computes all
// 3 N-tiles: X staged once (bf16 hi/lo), W tiles double-buffered via cp.async
// so global W loads overlap MMA of the previous N-tile.
// =============================================================================
#define BSTR 136                        // bf16 elems per smem row (272 B)
#define QA_H 0
#define QA_L 34816
#define QB0  69632                      // buf0: hi at +0, lo at +34816
#define QB1  139264                     // buf1
#define PC_SMEM 208896

__global__ void __launch_bounds__(256, 1) augru_precompute_mma(
    const float* __restrict__ X,
    const __nv_bfloat16* __restrict__ WThi,
    const __nv_bfloat16* __restrict__ WTlo,
    const int* __restrict__ seqlen,
    float* __restrict__ Gx, float* __restrict__ Cx)
{
    const int m0 = blockIdx.x * 128;
    {
        int b1 = m0 / T_;
        int t1 = m0 - b1 * T_;
        bool any = (t1 < seqlen[b1]);
        int b2 = (m0 + 127) / T_;
        if (b2 != b1) any = any || (seqlen[b2] > 0);
        if (!any) return;
    }

    extern __shared__ char smem[];
    const uint32_t sb = smem_u32(smem);
    const int tid = threadIdx.x;

    // cp.async one W N-tile (nt) into buffer at byte offset bufo
    auto issueB = [&](int nt, uint32_t bufo) {
#pragma unroll
        for (int q = 0; q < 8; q++) {              // 2048 hi chunks of 16B
            int f = q * 256 + tid;
            int n = f >> 4, c = f & 15;
            cpasync16(sb + bufo + n * 272 + c * 16,
                      &WThi[(size_t)(nt * 128 + n) * 256 + c * 8]);
        }
#pragma unroll
        for (int q = 0; q < 8; q++) {              // 2048 lo chunks
            int f = q * 256 + tid;
            int n = f >> 4, c = f & 15;
            cpasync16(sb + bufo + 34816 + n * 272 + c * 16,
                      &WTlo[(size_t)(nt * 128 + n) * 256 + c * 8]);
        }
        CPASYNC_COMMIT();
    };

    issueB(0, QB0);

    // ---- stage A (X rows) as bf16 hi/lo (overlaps B0 arrival) ----
#pragma unroll
    for (int q = 0; q < 16; q++) {
        int f = q * 256 + tid;
        int m = f >> 5, k = (f & 31) << 2;
        float4 v = *(const float4*)&X[(size_t)(m0 + m) * 128 + k];
        __nv_bfloat16 h0 = __float2bfloat16(v.x), h1 = __float2bfloat16(v.y);
        __nv_bfloat16 h2 = __float2bfloat16(v.z), h3 = __float2bfloat16(v.w);
        uint32_t hv0 = ((uint32_t)__bfloat16_as_ushort(h1) << 16) | __bfloat16_as_ushort(h0);
        uint32_t hv1 = ((uint32_t)__bfloat16_as_ushort(h3) << 16) | __bfloat16_as_ushort(h2);
        uint32_t lv0 = bf16pack(v.x - __bfloat162float(h0), v.y - __bfloat162float(h1));
        uint32_t lv1 = bf16pack(v.z - __bfloat162float(h2), v.w - __bfloat162float(h3));
        size_t o = ((size_t)m * BSTR + k) * 2;
        *(uint32_t*)(smem + QA_H + o)     = hv0;
        *(uint32_t*)(smem + QA_H + o + 4) = hv1;
        *(uint32_t*)(smem + QA_L + o)     = lv0;
        *(uint32_t*)(smem + QA_L + o + 4) = lv1;
    }

    issueB(1, QB1);

    const int wid = tid >> 5, lane = tid & 31;
    const int wm = wid >> 2, wn = wid & 3;
    const int g = lane >> 2, tig = lane & 3;

    // one N-tile of MMAs from buffer bufo, write epilogue direct to global
    auto mmaNT = [&](int nt, uint32_t bufo) {
        float acc[4][4][4];
#pragma unroll
        for (int i = 0; i < 4; i++)
#pragma unroll
            for (int j = 0; j < 4; j++)
#pragma unroll
                for (int e = 0; e < 4; e++) acc[i][j][e] = 0.0f;

        const char* Bh = smem + bufo;
        const char* Bl = smem + bufo + 34816;
#pragma unroll 1
        for (int prod = 0; prod < 3; prod++) {
            const char* Ab = smem + ((prod == 1) ? QA_L : QA_H);
            const char* Bb = (prod == 2) ? Bl : Bh;
#pragma unroll
            for (int ks = 0; ks < 8; ks++) {
                const int k0 = ks * 16 + 2 * tig;
                uint32_t a[4][4], b[4][2];
#pragma unroll
                for (int ma = 0; ma < 4; ma++) {
                    int r0 = wm * 64 + ma * 16 + g;
                    a[ma][0] = *(const uint32_t*)(Ab + ((size_t)r0 * BSTR + k0) * 2);
                    a[ma][1] = *(const uint32_t*)(Ab + ((size_t)(r0 + 8) * BSTR + k0) * 2);
                    a[ma][2] = *(const uint32_t*)(Ab + ((size_t)r0 * BSTR + k0 + 8) * 2);
                    a[ma][3] = *(const uint32_t*)(Ab + ((size_t)(r0 + 8) * BSTR + k0 + 8) * 2);
                }
#pragma unroll
                for (int na = 0; na < 4; na++) {
                    int n0 = wn * 32 + na * 8 + g;
                    b[na][0] = *(const uint32_t*)(Bb + ((size_t)n0 * BSTR + k0) * 2);
                    b[na][1] = *(const uint32_t*)(Bb + ((size_t)n0 * BSTR + k0 + 8) * 2);
                }
#pragma unroll
                for (int ma = 0; ma < 4; ma++)
#pragma unroll
                    for (int na = 0; na < 4; na++)
                        mma16816(acc[ma][na], a[ma][0], a[ma][1], a[ma][2], a[ma][3],
                                 b[na][0], b[na][1]);
            }
        }
        float* Out = (nt < 2) ? Gx : Cx;
        const int ldo = (nt < 2) ? 256 : 128;
        const int nc0 = (nt < 2) ? nt * 128 : 0;
#pragma unroll
        for (int ma = 0; ma < 4; ma++) {
            int r = m0 + wm * 64 + ma * 16 + g;
#pragma unroll
            for (int na = 0; na < 4; na++) {
                int col = nc0 + wn * 32 + na * 8 + 2 * tig;
                *(float2*)&Out[(size_t)r * ldo + col] = make_float2(acc[ma][na][0], acc[ma][na][1]);
                *(float2*)&Out[(size_t)(r + 8) * ldo + col] = make_float2(acc[ma][na][2], acc[ma][na][3]);
            }
        }
    };

    CPASYNC_WAIT(1);          // B0 arrived
    __syncthreads();          // + A staged by all threads
    mmaNT(0, QB0);
    __syncthreads();          // all warps done reading buf0
    issueB(2, QB0);
    CPASYNC_WAIT(1);          // B1 arrived
    __syncthreads();
    mmaNT(1, QB1);
    CPASYNC_WAIT(0);          // B2 arrived
    __syncthreads();
    mmaNT(2, QB0);
}

// =============================================================================
// Kernel 2: HMMA recurrence, balanced mapping. BPB=16, 128 blocks, 512 thr.
// Warp w owns h-cols [8w, 8w+8): computes reset col-frag 8w, update col-frag
// 128+8w, candidate col-frag 8w, and the h update — u and h never leave regs.
// ldmatrix fragment loads; split accumulators (chains 8/16).
// =============================================================================
#define BPB 16
#define THR 512
#define O_WGH 0
#define O_WGL 69632
#define O_WCH 139264
#define O_WCL 174080
#define O_AH  208896
#define O_AL  213248
#define REC_SMEM 217600

__global__ void __launch_bounds__(THR, 1) augru_recurrent_tc(
    const float* __restrict__ Gx, const float* __restrict__ Cx,
    const float* __restrict__ att,
    const int* __restrict__ perm, const int* __restrict__ sls,
    const __nv_bfloat16* __restrict__ WThi, const __nv_bfloat16* __restrict__ WTlo,
    const float* __restrict__ bg, const float* __restrict__ bc,
    float* __restrict__ out)
{
    extern __shared__ char smem[];
    const uint32_t sb = smem_u32(smem);
    const int tid = threadIdx.x;
    const int g0  = blockIdx.x * BPB;

    // ---- stage recurrent weights (h-part, k 128..255) as [col][272B] ----
    for (int i = tid; i < 256 * 16; i += THR) {
        int col = i >> 4, q = i & 15;
        *(uint4*)(smem + O_WGH + col * 272 + q * 16) = *(const uint4*)&WThi[(size_t)col * 256 + 128 + q * 8];
        *(uint4*)(smem + O_WGL + col * 272 + q * 16) = *(const uint4*)&WTlo[(size_t)col * 256 + 128 + q * 8];
    }
    for (int i = tid; i < 128 * 16; i += THR) {
        int col = i >> 4, q = i & 15;
        *(uint4*)(smem + O_WCH + col * 272 + q * 16) = *(const uint4*)&WThi[(size_t)(256 + col) * 256 + 128 + q * 8];
        *(uint4*)(smem + O_WCL + col * 272 + q * 16) = *(const uint4*)&WTlo[(size_t)(256 + col) * 256 + 128 + q * 8];
    }
    for (int i = tid; i < (4352 * 2) / 16; i += THR)    // h = 0 (hi+lo)
        *(uint4*)(smem + O_AH + i * 16) = make_uint4(0, 0, 0, 0);

    const int wid = tid >> 5, lane = tid & 31;
    const int g = lane >> 2, tig = lane & 3;
    const int cr = wid * 8 + 2 * tig;     // this lane's h-col pair base (0..126)

    // ldmatrix lane addresses
    //  A (16 rows x 128 k): m = lane>>3: m0=(r0-7,k0) m1=(r8-15,k0) m2=(r0-7,k0+8) m3=(r8-15,k0+8)
    const int am = lane >> 3;
    const uint32_t aoff = (uint32_t)(((am & 1) * 8 + (lane & 7)) * 272 + ((am >> 1) * 8) * 2);
    //  gate B x4: m0=(reset,k0) m1=(reset,k0+8) m2=(update,k0) m3=(update,k0+8)
    const int gwhich = am >> 1;
    const uint32_t gboff = (uint32_t)(((gwhich ? 128 + wid * 8 : wid * 8) + (lane & 7)) * 272
                                      + ((am & 1) * 8) * 2);
    //  cand B x2 (lanes 0-15): m0=(col,k0) m1=(col,k0+8)
    const int cl = lane & 15;
    const uint32_t cboff = (uint32_t)((wid * 8 + (cl & 7)) * 272 + ((cl >> 3) * 8) * 2);

    const int pb_lo = perm[g0 + g], pb_hi = perm[g0 + g + 8];
    const int sl_lo = sls[g0 + g],  sl_hi = sls[g0 + g + 8];
    const int maxsl = sls[g0];
    const size_t rb_lo = (size_t)pb_lo * T_, rb_hi = (size_t)pb_hi * T_;

    const float bgr0 = bg[cr], bgr1 = bg[cr + 1];
    const float bgu0 = bg[128 + cr], bgu1 = bg[128 + cr + 1];
    const float bc0 = bc[cr], bc1 = bc[cr + 1];

    float hreg[4] = {0.f, 0.f, 0.f, 0.f};   // (g,cr),(g,cr+1),(g+8,cr),(g+8,cr+1)

    // prefetch regs for step t
    float2 pgr0, pgr1, pgu0, pgu1, pcx0, pcx1;
    float patt0 = 0.f, patt1 = 0.f;
    pgr0 = pgr1 = pgu0 = pgu1 = pcx0 = pcx1 = make_float2(0.f, 0.f);
    if (maxsl > 0) {
        pgr0 = *(const float2*)&Gx[rb_lo * 256 + cr];
        pgr1 = *(const float2*)&Gx[rb_hi * 256 + cr];
        pgu0 = *(const float2*)&Gx[rb_lo * 256 + 128 + cr];
        pgu1 = *(const float2*)&Gx[rb_hi * 256 + 128 + cr];
        pcx0 = *(const float2*)&Cx[rb_lo * 128 + cr];
        pcx1 = *(const float2*)&Cx[rb_hi * 128 + cr];
        patt0 = att[rb_lo]; patt1 = att[rb_hi];
    }

    __syncthreads();

    for (int t = 0; t < maxsl; t++) {
        const float2 gr0 = pgr0, gr1 = pgr1, gu0 = pgu0, gu1 = pgu1, cx0 = pcx0, cx1 = pcx1;
        const float at0 = patt0, at1 = patt1;

        if (t + 1 < maxsl) {
            const size_t n0 = rb_lo + t + 1, n1 = rb_hi + t + 1;
            pgr0 = *(const float2*)&Gx[n0 * 256 + cr];
            pgr1 = *(const float2*)&Gx[n1 * 256 + cr];
            pgu0 = *(const float2*)&Gx[n0 * 256 + 128 + cr];
            pgu1 = *(const float2*)&Gx[n1 * 256 + 128 + cr];
            pcx0 = *(const float2*)&Cx[n0 * 128 + cr];
            pcx1 = *(const float2*)&Cx[n1 * 128 + cr];
            patt0 = att[n0]; patt1 = att[n1];
        }

        // ---- gate MMAs: reset frag (col 8w) + update frag (col 128+8w) ----
        float aR0[4] = {0, 0, 0, 0}, aR1[4] = {0, 0, 0, 0};
        float aU0[4] = {0, 0, 0, 0}, aU1[4] = {0, 0, 0, 0};
#pragma unroll
        for (int k0 = 0; k0 < 128; k0 += 16) {
            uint32_t ah0, ah1, ah2, ah3, al0, al1, al2, al3;
            ldsm_x4(ah0, ah1, ah2, ah3, sb + O_AH + aoff + k0 * 2);
            ldsm_x4(al0, al1, al2, al3, sb + O_AL + aoff + k0 * 2);
            uint32_t rh0, rh1, uh0, uh1, rl0, rl1, ul0, ul1;
            ldsm_x4(rh0, rh1, uh0, uh1, sb + O_WGH + gboff + k0 * 2);
            ldsm_x4(rl0, rl1, ul0, ul1, sb + O_WGL + gboff + k0 * 2);
            mma16816(aR0, ah0, ah1, ah2, ah3, rh0, rh1);     // hi*Whi
            mma16816(aR1, al0, al1, al2, al3, rh0, rh1);     // lo*Whi
            mma16816(aR1, ah0, ah1, ah2, ah3, rl0, rl1);     // hi*Wlo
            mma16816(aU0, ah0, ah1, ah2, ah3, uh0, uh1);
            mma16816(aU1, al0, al1, al2, al3, uh0, uh1);
            mma16816(aU1, ah0, ah1, ah2, ah3, ul0, ul1);
        }
        __syncthreads();   // all gate reads of A done

        // ---- epilogue 1: r, u (regs), rh -> A ----
        float u0 = at0 * sigmoid_fast(aU0[0] + aU1[0] + gu0.x + bgu0);
        float u1 = at0 * sigmoid_fast(aU0[1] + aU1[1] + gu0.y + bgu1);
        float u2 = at1 * sigmoid_fast(aU0[2] + aU1[2] + gu1.x + bgu0);
        float u3 = at1 * sigmoid_fast(aU0[3] + aU1[3] + gu1.y + bgu1);
        {
            float r0 = sigmoid_fast(aR0[0] + aR1[0] + gr0.x + bgr0);
            float r1 = sigmoid_fast(aR0[1] + aR1[1] + gr0.y + bgr1);
            float r2 = sigmoid_fast(aR0[2] + aR1[2] + gr1.x + bgr0);
            float r3 = sigmoid_fast(aR0[3] + aR1[3] + gr1.y + bgr1);
            float rh0 = r0 * hreg[0], rh1 = r1 * hreg[1];
            float rh2 = r2 * hreg[2], rh3 = r3 * hreg[3];
            uint32_t hlo = bf16pack(rh0, rh1), hhi = bf16pack(rh2, rh3);
            *(uint32_t*)(smem + O_AH + g * 272 + cr * 2)       = hlo;
            *(uint32_t*)(smem + O_AH + (g + 8) * 272 + cr * 2) = hhi;
            *(uint32_t*)(smem + O_AL + g * 272 + cr * 2)       = bf16res(rh0, rh1, hlo);
            *(uint32_t*)(smem + O_AL + (g + 8) * 272 + cr * 2) = bf16res(rh2, rh3, hhi);
        }
        __syncthreads();   // rh visible

        // ---- candidate MMAs: col-frag 8w, A = rh ----
        float aC0[4] = {0, 0, 0, 0}, aC1[4] = {0, 0, 0, 0};
#pragma unroll
        for (int k0 = 0; k0 < 128; k0 += 16) {
            uint32_t ah0, ah1, ah2, ah3, al0, al1, al2, al3;
            ldsm_x4(ah0, ah1, ah2, ah3, sb + O_AH + aoff + k0 * 2);
            ldsm_x4(al0, al1, al2, al3, sb + O_AL + aoff + k0 * 2);
            uint32_t ch0, ch1, cl0, cl1;
            ldsm_x2(ch0, ch1, sb + O_WCH + cboff + k0 * 2);
            ldsm_x2(cl0, cl1, sb + O_WCL + cboff + k0 * 2);
            mma16816(aC0, ah0, ah1, ah2, ah3, ch0, ch1);
            mma16816(aC1, al0, al1, al2, al3, ch0, ch1);
            mma16816(aC1, ah0, ah1, ah2, ah3, cl0, cl1);
        }
        __syncthreads();   // candidate reads of A done

        // ---- epilogue 2: h update + masked output + new h -> A ----
        {
            float c0 = tanh_fast(aC0[0] + aC1[0] + cx0.x + bc0);
            float c1 = tanh_fast(aC0[1] + aC1[1] + cx0.y + bc1);
            float c2 = tanh_fast(aC0[2] + aC1[2] + cx1.x + bc0);
            float c3 = tanh_fast(aC0[3] + aC1[3] + cx1.y + bc1);
            float hn0 = (1.0f - u0) * hreg[0] + u0 * c0;
            float hn1 = (1.0f - u1) * hreg[1] + u1 * c1;
            float hn2 = (1.0f - u2) * hreg[2] + u2 * c2;
            float hn3 = (1.0f - u3) * hreg[3] + u3 * c3;
            const bool v_lo = (t < sl_lo), v_hi = (t < sl_hi);
            *(float2*)&out[(rb_lo + t) * 128 + cr] = v_lo ? make_float2(hn0, hn1)
                                                          : make_float2(0.f, 0.f);
            *(float2*)&out[(rb_hi + t) * 128 + cr] = v_hi ? make_float2(hn2, hn3)
                                                          : make_float2(0.f, 0.f);
            hreg[0] = v_lo ? hn0 : hreg[0];
            hreg[1] = v_lo ? hn1 : hreg[1];
            hreg[2] = v_hi ? hn2 : hreg[2];
            hreg[3] = v_hi ? hn3 : hreg[3];
            uint32_t hlo = bf16pack(hreg[0], hreg[1]), hhi = bf16pack(hreg[2], hreg[3]);
            *(uint32_t*)(smem + O_AH + g * 272 + cr * 2)       = hlo;
            *(uint32_t*)(smem + O_AH + (g + 8) * 272 + cr * 2) = hhi;
            *(uint32_t*)(smem + O_AL + g * 272 + cr * 2)       = bf16res(hreg[0], hreg[1], hlo);
            *(uint32_t*)(smem + O_AL + (g + 8) * 272 + cr * 2) = bf16res(hreg[2], hreg[3], hhi);
        }
        __syncthreads();   // new h visible for next gate phase
    }

    // ---- zero tail: t in [maxsl, T) for all 16 batches ----
    for (int idx = tid; idx < (T_ - maxsl) * BPB * 32; idx += THR) {
        int t  = maxsl + idx / (BPB * 32);
        int r  = idx % (BPB * 32);
        int i  = r >> 5;
        int j4 = (r & 31) << 2;
        int b  = perm[g0 + i];
        *(float4*)&out[((size_t)b * T_ + t) * 128 + j4] = make_float4(0.f, 0.f, 0.f, 0.f);
    }
}

// =============================================================================
extern "C" void kernel_launch(void* const* d_in, const int* in_sizes, int n_in,
                              void* d_out, int out_size)
{
    (void)in_sizes; (void)n_in; (void)out_size;
    const float* X      = (const float*)d_in[0];
    const float* att    = (const float*)d_in[1];
    const int*   seqlen = (const int*)  d_in[2];
    const float* Wg     = (const float*)d_in[3];
    const float* bg     = (const float*)d_in[4];
    const float* Wc     = (const float*)d_in[5];
    const float* bc     = (const float*)d_in[6];
    float* out          = (float*)d_out;

    float *Gx, *Cx; int *perm, *sls; __nv_bfloat16 *WThi, *WTlo;
    cudaGetSymbolAddress((void**)&Gx,   g_Gx);
    cudaGetSymbolAddress((void**)&Cx,   g_Cx);
    cudaGetSymbolAddress((void**)&perm, g_perm);
    cudaGetSymbolAddress((void**)&sls,  g_sls);
    cudaGetSymbolAddress((void**)&WThi, g_WThi);
    cudaGetSymbolAddress((void**)&WTlo, g_WTlo);

    augru_wprep<<<12, 256>>>(Wg, Wc, WThi, WTlo);
    augru_sort<<<B_ / 256, 256>>>(seqlen, perm, sls);

    cudaFuncSetAttribute(augru_precompute_mma,
                         cudaFuncAttributeMaxDynamicSharedMemorySize, PC_SMEM);
    augru_precompute_mma<<<M_ / 128, 256, PC_SMEM>>>(X, WThi, WTlo, seqlen, Gx, Cx);

    cudaFuncSetAttribute(augru_recurrent_tc,
                         cudaFuncAttributeMaxDynamicSharedMemorySize, REC_SMEM);
    augru_recurrent_tc<<<B_ / BPB, THR, REC_SMEM>>>(Gx, Cx, att, perm, sls,
                                                    WThi, WTlo, bg, bc, out);
}